// round 17
// baseline (speedup 1.0000x reference)
#include <cuda_runtime.h>
#include <cuda_fp16.h>
#include <math.h>
#include <stdint.h>

// Problem constants
#define Bb   16
#define Tt   512
#define Dd   2048
#define Hh   4
#define HDd  512
#define BT   8192          // B*T rows
#define NQKV 6144          // 3*D
#define DFF  8192          // 4*D
#define LNEPS 1e-5f

// ---------------------------------------------------------------------------
// Scratch (static __device__ arrays; no allocation allowed)
// ---------------------------------------------------------------------------
__device__ __align__(128) __half g_lnh[(size_t)BT * Dd];
__device__ __align__(128) __half g_wqkvh[(size_t)NQKV * Dd];      // [6144][2048] K-major
__device__ __align__(128) __half g_qkvh[(size_t)BT * NQKV];
__device__ __align__(128) float  g_scores[(size_t)Bb * Hh * Tt * Tt];
__device__ __align__(128) __half g_probs[(size_t)Bb * Hh * Tt * Tt];
__device__ __align__(128) __half g_ctxh[(size_t)BT * Dd];
__device__ __align__(128) __half g_ffnh[(size_t)BT * DFF];
__device__ __align__(128) __half g_woth[(size_t)Dd * Dd];
__device__ __align__(128) __half g_w1th[(size_t)DFF * Dd];
__device__ __align__(128) __half g_w2th[(size_t)Dd * DFF];

// ---------------------------------------------------------------------------
// PTX helpers
// ---------------------------------------------------------------------------
__device__ __forceinline__ uint32_t smem_u32(const void* p) {
    uint32_t a;
    asm("{ .reg .u64 t; cvta.to.shared.u64 t, %1; cvt.u32.u64 %0, t; }"
        : "=r"(a) : "l"(p));
    return a;
}
__device__ __forceinline__ void cp_async16(uint32_t smem_dst, const void* gmem_src) {
    asm volatile("cp.async.cg.shared.global [%0], [%1], 16;\n" :: "r"(smem_dst), "l"(gmem_src));
}
__device__ __forceinline__ void cp_commit() {
    asm volatile("cp.async.commit_group;\n");
}
template<int N>
__device__ __forceinline__ void cp_wait() {
    asm volatile("cp.async.wait_group %0;\n" :: "n"(N));
}
__device__ __forceinline__ void mma_f16(float* c, const uint32_t* a, const uint32_t* b) {
    asm volatile(
        "mma.sync.aligned.m16n8k16.row.col.f32.f16.f16.f32 "
        "{%0,%1,%2,%3}, {%4,%5,%6,%7}, {%8,%9}, {%0,%1,%2,%3};"
        : "+f"(c[0]), "+f"(c[1]), "+f"(c[2]), "+f"(c[3])
        : "r"(a[0]), "r"(a[1]), "r"(a[2]), "r"(a[3]), "r"(b[0]), "r"(b[1]));
}
__device__ __forceinline__ void ldsm_x4(uint32_t& r0, uint32_t& r1,
                                        uint32_t& r2, uint32_t& r3,
                                        uint32_t addr) {
    asm volatile(
        "ldmatrix.sync.aligned.m8n8.x4.shared.b16 {%0,%1,%2,%3}, [%4];"
        : "=r"(r0), "=r"(r1), "=r"(r2), "=r"(r3) : "r"(addr));
}
__device__ __forceinline__ void ldsm_x2t(uint32_t& r0, uint32_t& r1, uint32_t addr) {
    asm volatile(
        "ldmatrix.sync.aligned.m8n8.x2.trans.shared.b16 {%0,%1}, [%2];"
        : "=r"(r0), "=r"(r1) : "r"(addr));
}

// ---------------------------------------------------------------------------
// Weight transpose + fp16 convert:  out[N][K] = half(in[K][N])
// ---------------------------------------------------------------------------
__global__ void transpose_h(const float* __restrict__ in,
                            __half* __restrict__ out, int K, int N) {
    __shared__ float t[64][33];
    int n0 = blockIdx.x * 32, k0 = blockIdx.y * 64;
    int lx = threadIdx.x, ly = threadIdx.y;
    #pragma unroll
    for (int r = 0; r < 64; r += 8)
        t[r + ly][lx] = in[(size_t)(k0 + r + ly) * N + n0 + lx];
    __syncthreads();
    #pragma unroll
    for (int r = 0; r < 32; r += 8) {
        int row = r + ly;
        *(__half2*)&out[(size_t)(n0 + row) * K + k0 + 2 * lx] =
            __floats2half2_rn(t[2 * lx][row], t[2 * lx + 1][row]);
    }
}

// Repack+transpose Wq/Wk/Wv [H,D,HD] -> half [3D][D] K-major.
__global__ void repack_qkv_t_h(const float* __restrict__ Wq,
                               const float* __restrict__ Wk,
                               const float* __restrict__ Wv,
                               __half* __restrict__ out) {
    __shared__ float t[64][33];
    int z = blockIdx.z;
    int sel = z >> 2, h = z & 3;
    const float* W = (sel == 0 ? Wq : sel == 1 ? Wk : Wv) + (size_t)h * Dd * HDd;
    int c0 = blockIdx.x * 32, k0 = blockIdx.y * 64;
    int lx = threadIdx.x, ly = threadIdx.y;
    #pragma unroll
    for (int r = 0; r < 64; r += 8)
        t[r + ly][lx] = W[(size_t)(k0 + r + ly) * HDd + c0 + lx];
    __syncthreads();
    int nbase = sel * 2048 + h * 512 + c0;
    #pragma unroll
    for (int r = 0; r < 32; r += 8) {
        int row = r + ly;
        *(__half2*)&out[(size_t)(nbase + row) * Dd + k0 + 2 * lx] =
            __floats2half2_rn(t[2 * lx][row], t[2 * lx + 1][row]);
    }
}

// ---------------------------------------------------------------------------
// LayerNorm: one block per row (D=2048), 256 threads. fp16 output.
// ---------------------------------------------------------------------------
__global__ void ln_kernel_h(const float* __restrict__ x,
                            const float* __restrict__ g,
                            const float* __restrict__ b,
                            __half* __restrict__ out) {
    int row = blockIdx.x;
    int t   = threadIdx.x;
    const float4* xr = (const float4*)(x + (size_t)row * Dd);
    float4 v0 = xr[t];
    float4 v1 = xr[t + 256];
    float s  = v0.x + v0.y + v0.z + v0.w + v1.x + v1.y + v1.z + v1.w;
    float sq = v0.x*v0.x + v0.y*v0.y + v0.z*v0.z + v0.w*v0.w
             + v1.x*v1.x + v1.y*v1.y + v1.z*v1.z + v1.w*v1.w;
    #pragma unroll
    for (int o = 16; o; o >>= 1) {
        s  += __shfl_xor_sync(0xffffffffu, s,  o);
        sq += __shfl_xor_sync(0xffffffffu, sq, o);
    }
    __shared__ float ss[8], ssq[8];
    int w = t >> 5;
    if ((t & 31) == 0) { ss[w] = s; ssq[w] = sq; }
    __syncthreads();
    float S = 0.f, SQ = 0.f;
    #pragma unroll
    for (int i = 0; i < 8; i++) { S += ss[i]; SQ += ssq[i]; }
    float mean = S * (1.f / Dd);
    float var  = SQ * (1.f / Dd) - mean * mean;
    float rstd = rsqrtf(var + LNEPS);

    const float4* gr = (const float4*)g;
    const float4* br = (const float4*)b;
    __half2* o2 = (__half2*)(out + (size_t)row * Dd);
    float4 gv = gr[t], bv = br[t];
    o2[2 * t]     = __floats2half2_rn((v0.x - mean) * rstd * gv.x + bv.x,
                                      (v0.y - mean) * rstd * gv.y + bv.y);
    o2[2 * t + 1] = __floats2half2_rn((v0.z - mean) * rstd * gv.z + bv.z,
                                      (v0.w - mean) * rstd * gv.w + bv.w);
    gv = gr[t + 256]; bv = br[t + 256];
    o2[2 * (t + 256)]     = __floats2half2_rn((v1.x - mean) * rstd * gv.x + bv.x,
                                              (v1.y - mean) * rstd * gv.y + bv.y);
    o2[2 * (t + 256) + 1] = __floats2half2_rn((v1.z - mean) * rstd * gv.z + bv.z,
                                              (v1.w - mean) * rstd * gv.w + bv.w);
}

#define H_ROWH 72                       // halves per smem row (64 + 8 pad)

// ---------------------------------------------------------------------------
// fp16 tensor-core GEMM (weight GEMMs): C[M,N] = A[M,K] @ Bt[N,K]^T
// CTA tile 128(M) x 256(N), 512 threads = 16 warps (4m x 4n), warp 32x64.
// K-chunk 64, 3-stage cp.async, single __syncthreads per chunk, 1 CTA/SM
// (16 warps/SM, same as 2x256). A-frags ldmatrix.x4; B-frags PAIRED
// ldmatrix.x4 (one x4 = two n8k16 frags). 25% less L2 traffic per FLOP.
// ---------------------------------------------------------------------------
#define G_A_TILE (128 * H_ROWH * 2)              // 18432
#define G_B_TILE (256 * H_ROWH * 2)              // 36864
#define G_STAGE_BYTES (G_A_TILE + G_B_TILE)      // 55296
#define G_SMEM_BYTES (3 * G_STAGE_BYTES)         // 165888

__global__ void __launch_bounds__(512, 1)
hgemm(const __half* __restrict__ A, int lda,
      const __half* __restrict__ B, int ldb,
      void* __restrict__ Cvoid, int ldc,
      int K,
      const float* __restrict__ bias,
      const float* __restrict__ resid, int ldr,
      int relu, int out_half) {
    extern __shared__ __align__(16) char sm_[];
    const uint32_t smem_u = smem_u32(sm_);

    const int m0 = blockIdx.y * 128;
    const int n0 = blockIdx.x * 256;
    const int tid  = threadIdx.x;
    const int lane = tid & 31;
    const int wid  = tid >> 5;          // 0..15
    const int g  = lane >> 2;
    const int t4 = lane & 3;
    const int mw = (wid >> 2) * 32;     // warp m offset (4 rows of warps)
    const int nw = (wid & 3) * 64;      // warp n offset (4 cols of warps)

    // fill: A 128x64 halves = 1024 chunks (2/thread); B 256x64 = 2048 (4/thread)
    const int c_row = tid >> 3;         // 0..63
    const int c_off = (tid & 7) * 8;

    auto issue = [&](int kt, int s) {
        const uint32_t sa = smem_u + s * G_STAGE_BYTES;
        const uint32_t sb = sa + G_A_TILE;
        const __half* ap = A + (size_t)(m0) * lda + kt * 64 + c_off;
        const __half* bp = B + (size_t)(n0) * ldb + kt * 64 + c_off;
        #pragma unroll
        for (int p = 0; p < 2; p++) {
            int r = c_row + p * 64;
            cp_async16(sa + (uint32_t)(r * H_ROWH + c_off) * 2,
                       ap + (size_t)r * lda);
        }
        #pragma unroll
        for (int p = 0; p < 4; p++) {
            int r = c_row + p * 64;
            cp_async16(sb + (uint32_t)(r * H_ROWH + c_off) * 2,
                       bp + (size_t)r * ldb);
        }
        cp_commit();
    };

    // ldmatrix lane offsets (halves)
    const uint32_t a_lane_off =
        (uint32_t)((mw + (lane & 15)) * H_ROWH + (lane >> 4) * 8);
    // paired-B x4: rows n + (l&7) + ((l>>4)<<3), col ((l>>3)&1)*8
    const uint32_t b_lane_off =
        (uint32_t)((nw + (lane & 7) + ((lane >> 4) << 3)) * H_ROWH
                   + ((lane >> 3) & 1) * 8);

    float acc[2][8][4];
    #pragma unroll
    for (int mi = 0; mi < 2; mi++)
        #pragma unroll
        for (int ni = 0; ni < 8; ni++)
            #pragma unroll
            for (int q = 0; q < 4; q++) acc[mi][ni][q] = 0.f;

    const int nk = K >> 6;
    issue(0, 0);
    issue(1, 1);

    for (int kt = 0; kt < nk; kt++) {
        const int cur = kt % 3;
        if (kt + 1 < nk) cp_wait<1>();
        else             cp_wait<0>();
        __syncthreads();
        if (kt + 2 < nk) issue(kt + 2, (kt + 2) % 3);

        const uint32_t sa_u = smem_u + cur * G_STAGE_BYTES;
        const uint32_t sb_u = sa_u + G_A_TILE;
        #pragma unroll
        for (int ks = 0; ks < 4; ks++) {
            uint32_t af[2][4], bf[8][2];
            #pragma unroll
            for (int mi = 0; mi < 2; mi++)
                ldsm_x4(af[mi][0], af[mi][1], af[mi][2], af[mi][3],
                        sa_u + 2u * (a_lane_off + mi * 16 * H_ROWH + ks * 16));
            #pragma unroll
            for (int pr = 0; pr < 4; pr++)
                ldsm_x4(bf[2*pr][0], bf[2*pr][1], bf[2*pr+1][0], bf[2*pr+1][1],
                        sb_u + 2u * (b_lane_off + pr * 16 * H_ROWH + ks * 16));
            #pragma unroll
            for (int mi = 0; mi < 2; mi++)
                #pragma unroll
                for (int ni = 0; ni < 8; ni++)
                    mma_f16(acc[mi][ni], af[mi], bf[ni]);
        }
    }

    // Epilogue
    float* Cf = (float*)Cvoid;
    __half* Ch = (__half*)Cvoid;
    #pragma unroll
    for (int mi = 0; mi < 2; mi++) {
        const int r0 = m0 + mw + mi * 16 + g;
        #pragma unroll
        for (int ni = 0; ni < 8; ni++) {
            const int c0 = n0 + nw + ni * 8 + t4 * 2;
            float bb0 = 0.f, bb1 = 0.f;
            if (bias) { bb0 = bias[c0]; bb1 = bias[c0 + 1]; }
            float v0 = acc[mi][ni][0] + bb0;
            float v1 = acc[mi][ni][1] + bb1;
            float v2 = acc[mi][ni][2] + bb0;
            float v3 = acc[mi][ni][3] + bb1;
            if (resid) {
                const float* R0 = resid + (size_t)r0 * ldr + c0;
                const float* R1 = resid + (size_t)(r0 + 8) * ldr + c0;
                v0 += R0[0]; v1 += R0[1];
                v2 += R1[0]; v3 += R1[1];
            }
            if (relu) {
                v0 = fmaxf(v0, 0.f); v1 = fmaxf(v1, 0.f);
                v2 = fmaxf(v2, 0.f); v3 = fmaxf(v3, 0.f);
            }
            if (out_half) {
                *(__half2*)&Ch[(size_t)r0 * ldc + c0]       = __floats2half2_rn(v0, v1);
                *(__half2*)&Ch[(size_t)(r0 + 8) * ldc + c0] = __floats2half2_rn(v2, v3);
            } else {
                *(float2*)&Cf[(size_t)r0 * ldc + c0]       = make_float2(v0, v1);
                *(float2*)&Cf[(size_t)(r0 + 8) * ldc + c0] = make_float2(v2, v3);
            }
        }
    }
}

// ---------------------------------------------------------------------------
// Scores: 128x128 tiles, 256 threads (R16 shape), causal skip, paired-x4 B.
// ---------------------------------------------------------------------------
#define S_TILE_BYTES (128 * H_ROWH * 2)
#define S_STAGE_BYTES (2 * S_TILE_BYTES)
#define S_SMEM_BYTES (3 * S_STAGE_BYTES)   // 110592

__global__ void __launch_bounds__(256, 2)
scores_h(const __half* __restrict__ QKVh, float* __restrict__ S) {
    const int m0 = blockIdx.y * 128;
    const int n0 = blockIdx.x * 128;
    if (n0 > m0) return;

    extern __shared__ __align__(16) char sm_[];
    const uint32_t smem_u = smem_u32(sm_);

    const int z = blockIdx.z;
    const int bb = z >> 2, hh = z & 3;
    const __half* A = QKVh + (size_t)(bb * Tt) * NQKV + hh * HDd;   // q
    const __half* B = A + Dd;                                       // k
    float* Cs = S + (size_t)z * Tt * Tt;

    const int tid  = threadIdx.x;
    const int lane = tid & 31;
    const int wid  = tid >> 5;
    const int g  = lane >> 2;
    const int t4 = lane & 3;
    const int mw = (wid >> 2) * 64;
    const int nw = (wid & 3) * 32;

    const int c_row = tid >> 3;
    const int c_off = (tid & 7) * 8;

    auto issue = [&](int kt, int s) {
        const uint32_t sa = smem_u + s * S_STAGE_BYTES;
        const uint32_t sb = sa + S_TILE_BYTES;
        const __half* ap = A + (size_t)(m0) * NQKV + kt * 64 + c_off;
        const __half* bp = B + (size_t)(n0) * NQKV + kt * 64 + c_off;
        #pragma unroll
        for (int p = 0; p < 4; p++) {
            int r = c_row + p * 32;
            cp_async16(sa + (uint32_t)(r * H_ROWH + c_off) * 2,
                       ap + (size_t)r * NQKV);
            cp_async16(sb + (uint32_t)(r * H_ROWH + c_off) * 2,
                       bp + (size_t)r * NQKV);
        }
        cp_commit();
    };

    const uint32_t a_lane_off =
        (uint32_t)((mw + (lane & 15)) * H_ROWH + (lane >> 4) * 8);
    const uint32_t b_lane_off =
        (uint32_t)((nw + (lane & 7) + ((lane >> 4) << 3)) * H_ROWH
                   + ((lane >> 3) & 1) * 8);

    float acc[4][4][4];
    #pragma unroll
    for (int mi = 0; mi < 4; mi++)
        #pragma unroll
        for (int ni = 0; ni < 4; ni++)
            #pragma unroll
            for (int q = 0; q < 4; q++) acc[mi][ni][q] = 0.f;

    const int nk = HDd >> 6;   // 8
    issue(0, 0);
    issue(1, 1);

    for (int kt = 0; kt < nk; kt++) {
        const int cur = kt % 3;
        if (kt + 1 < nk) cp_wait<1>();
        else             cp_wait<0>();
        __syncthreads();
        if (kt + 2 < nk) issue(kt + 2, (kt + 2) % 3);

        const uint32_t sa_u = smem_u + cur * S_STAGE_BYTES;
        const uint32_t sb_u = sa_u + S_TILE_BYTES;
        #pragma unroll
        for (int ks = 0; ks < 4; ks++) {
            uint32_t af[4][4], bf[4][2];
            #pragma unroll
            for (int mi = 0; mi < 4; mi++)
                ldsm_x4(af[mi][0], af[mi][1], af[mi][2], af[mi][3],
                        sa_u + 2u * (a_lane_off + mi * 16 * H_ROWH + ks * 16));
            #pragma unroll
            for (int pr = 0; pr < 2; pr++)
                ldsm_x4(bf[2*pr][0], bf[2*pr][1], bf[2*pr+1][0], bf[2*pr+1][1],
                        sb_u + 2u * (b_lane_off + pr * 16 * H_ROWH + ks * 16));
            #pragma unroll
            for (int mi = 0; mi < 4; mi++)
                #pragma unroll
                for (int ni = 0; ni < 4; ni++)
                    mma_f16(acc[mi][ni], af[mi], bf[ni]);
        }
    }

    const float scale = 0.044194173824159216f;
    #pragma unroll
    for (int mi = 0; mi < 4; mi++) {
        const int r0 = m0 + mw + mi * 16 + g;
        #pragma unroll
        for (int ni = 0; ni < 4; ni++) {
            const int c0 = n0 + nw + ni * 8 + t4 * 2;
            float v0 = (c0     > r0)     ? -1e30f : acc[mi][ni][0] * scale;
            float v1 = (c0 + 1 > r0)     ? -1e30f : acc[mi][ni][1] * scale;
            float v2 = (c0     > r0 + 8) ? -1e30f : acc[mi][ni][2] * scale;
            float v3 = (c0 + 1 > r0 + 8) ? -1e30f : acc[mi][ni][3] * scale;
            *(float2*)&Cs[(size_t)r0 * Tt + c0]       = make_float2(v0, v1);
            *(float2*)&Cs[(size_t)(r0 + 8) * Tt + c0] = make_float2(v2, v3);
        }
    }
}

// ---------------------------------------------------------------------------
// ctx GEMM (R16): C = probs @ V, v from packed QKV via trans-ldmatrix,
// causal K-limit. 128x128, 256 threads, K-chunk 64, 3 stages.
// ---------------------------------------------------------------------------
#define CB_ROWH 136
#define CB_TILE_BYTES (64 * CB_ROWH * 2)               // 17408
#define C_STAGE_BYTES (S_TILE_BYTES + CB_TILE_BYTES)   // 35840
#define C_SMEM_BYTES (3 * C_STAGE_BYTES)               // 107520

__global__ void __launch_bounds__(256, 2)
ctx_hgemm(const __half* __restrict__ P,
          const __half* __restrict__ QKVh,
          __half* __restrict__ C) {
    extern __shared__ __align__(16) char sm_[];
    const uint32_t smem_u = smem_u32(sm_);

    const int z = blockIdx.z;
    const int bb = z >> 2, hh = z & 3;
    const __half* A = P + (size_t)z * Tt * Tt;
    const __half* B = QKVh + (size_t)(bb * Tt) * NQKV + 4096 + hh * HDd;
    __half* Cc = C + (size_t)(bb * Tt) * Dd + hh * HDd;

    const int m0 = blockIdx.y * 128;
    const int n0 = blockIdx.x * 128;
    const int tid  = threadIdx.x;
    const int lane = tid & 31;
    const int wid  = tid >> 5;
    const int g  = lane >> 2;
    const int t4 = lane & 3;
    const int mw = (wid >> 2) * 64;
    const int nw = (wid & 3) * 32;

    const int K = m0 + 128;

    const int c_row = tid >> 3;
    const int c_off = (tid & 7) * 8;
    const int b_row = tid >> 4;
    const int b_c8  = (tid & 15) * 8;

    auto issue = [&](int kt, int s) {
        const uint32_t sa = smem_u + s * C_STAGE_BYTES;
        const uint32_t sb = sa + S_TILE_BYTES;
        const __half* ap = A + (size_t)(m0) * Tt + kt * 64 + c_off;
        #pragma unroll
        for (int p = 0; p < 4; p++) {
            int r = c_row + p * 32;
            cp_async16(sa + (uint32_t)(r * H_ROWH + c_off) * 2,
                       ap + (size_t)r * Tt);
        }
        const __half* bp = B + (size_t)(kt * 64) * NQKV + n0 + b_c8;
        #pragma unroll
        for (int p = 0; p < 4; p++) {
            int r = b_row + p * 16;
            cp_async16(sb + (uint32_t)(r * CB_ROWH + b_c8) * 2,
                       bp + (size_t)r * NQKV);
        }
        cp_commit();
    };

    const uint32_t a_lane_off =
        (uint32_t)((mw + (lane & 15)) * H_ROWH + (lane >> 4) * 8);
    const uint32_t b_lane_row = (uint32_t)(lane & 15);

    float acc[4][4][4];
    #pragma unroll
    for (int mi = 0; mi < 4; mi++)
        #pragma unroll
        for (int ni = 0; ni < 4; ni++)
            #pragma unroll
            for (int q = 0; q < 4; q++) acc[mi][ni][q] = 0.f;

    const int nk = K >> 6;
    issue(0, 0);
    issue(1, 1);

    for (int kt = 0; kt < nk; kt++) {
        const int cur = kt % 3;
        if (kt + 1 < nk) cp_wait<1>();
        else             cp_wait<0>();
        __syncthreads();
        if (kt + 2 < nk) issue(kt + 2, (kt + 2) % 3);

        const uint32_t sa_u = smem_u + cur * C_STAGE_BYTES;
        const uint32_t sb_u = sa_u + S_TILE_BYTES;
        #pragma unroll
        for (int ks = 0; ks < 4; ks++) {
            uint32_t af[4][4], bf[4][2];
            #pragma unroll
            for (int mi = 0; mi < 4; mi++)
                ldsm_x4(af[mi][0], af[mi][1], af[mi][2], af[mi][3],
                        sa_u + 2u * (a_lane_off + mi * 16 * H_ROWH + ks * 16));
            #pragma unroll
            for (int ni = 0; ni < 4; ni++)
                ldsm_x2t(bf[ni][0], bf[ni][1],
                         sb_u + 2u * ((ks * 16 + b_lane_row) * CB_ROWH
                                      + nw + ni * 8));
            #pragma unroll
            for (int mi = 0; mi < 4; mi++)
                #pragma unroll
                for (int ni = 0; ni < 4; ni++)
                    mma_f16(acc[mi][ni], af[mi], bf[ni]);
        }
    }

    #pragma unroll
    for (int mi = 0; mi < 4; mi++) {
        const int r0 = m0 + mw + mi * 16 + g;
        #pragma unroll
        for (int ni = 0; ni < 4; ni++) {
            const int c0 = n0 + nw + ni * 8 + t4 * 2;
            *(__half2*)&Cc[(size_t)r0 * Dd + c0] =
                __floats2half2_rn(acc[mi][ni][0], acc[mi][ni][1]);
            *(__half2*)&Cc[(size_t)(r0 + 8) * Dd + c0] =
                __floats2half2_rn(acc[mi][ni][2], acc[mi][ni][3]);
        }
    }
}

// ---------------------------------------------------------------------------
// Row softmax (fp32 in) -> fp16 probs, causal reads + writes.
// ---------------------------------------------------------------------------
__global__ void softmax_h(const float* __restrict__ S, __half* __restrict__ P) {
    int row = blockIdx.x;
    int i = row & (Tt - 1);
    int t = threadIdx.x;
    const float4* p = (const float4*)(S + (size_t)row * Tt);
    float4 v;
    if (4 * t <= i) {
        v = p[t];
    } else {
        v = make_float4(-1e30f, -1e30f, -1e30f, -1e30f);
    }
    float m = fmaxf(fmaxf(v.x, v.y), fmaxf(v.z, v.w));
    #pragma unroll
    for (int o = 16; o; o >>= 1) m = fmaxf(m, __shfl_xor_sync(0xffffffffu, m, o));
    __shared__ float sm[4], ssum[4];
    int w = t >> 5;
    if ((t & 31) == 0) sm[w] = m;
    __syncthreads();
    m = fmaxf(fmaxf(sm[0], sm[1]), fmaxf(sm[2], sm[3]));
    v.x = expf(v.x - m); v.y = expf(v.y - m);
    v.z = expf(v.z - m); v.w = expf(v.w - m);
    float s = v.x + v.y + v.z + v.w;
    #pragma unroll
    for (int o = 16; o; o >>= 1) s += __shfl_xor_sync(0xffffffffu, s, o);
    if ((t & 31) == 0) ssum[w] = s;
    __syncthreads();
    s = ssum[0] + ssum[1] + ssum[2] + ssum[3];
    float inv = 1.f / s;
    const int lim4 = (((i >> 7) + 1) << 7) >> 2;
    if (t < lim4) {
        __half2* ph = (__half2*)(P + (size_t)row * Tt);
        ph[2 * t]     = __floats2half2_rn(v.x * inv, v.y * inv);
        ph[2 * t + 1] = __floats2half2_rn(v.z * inv, v.w * inv);
    }
}

// ---------------------------------------------------------------------------
// Host launcher
// ---------------------------------------------------------------------------
extern "C" void kernel_launch(void* const* d_in, const int* in_sizes, int n_in,
                              void* d_out, int out_size) {
    const float* x   = (const float*)d_in[0];
    const float* Wq  = (const float*)d_in[1];
    const float* Wk  = (const float*)d_in[2];
    const float* Wv  = (const float*)d_in[3];
    const float* Wo  = (const float*)d_in[4];
    const float* bo  = (const float*)d_in[5];
    const float* W1  = (const float*)d_in[6];
    const float* b1  = (const float*)d_in[7];
    const float* W2  = (const float*)d_in[8];
    const float* b2  = (const float*)d_in[9];
    const float* g1  = (const float*)d_in[10];
    const float* be1 = (const float*)d_in[11];
    const float* g2  = (const float*)d_in[12];
    const float* be2 = (const float*)d_in[13];
    float* out = (float*)d_out;

    __half *p_lnh, *p_wqkvh, *p_qkvh, *p_probs, *p_ctxh, *p_ffnh,
           *p_woth, *p_w1th, *p_w2th;
    float *p_sc;
    cudaGetSymbolAddress((void**)&p_lnh,   g_lnh);
    cudaGetSymbolAddress((void**)&p_wqkvh, g_wqkvh);
    cudaGetSymbolAddress((void**)&p_qkvh,  g_qkvh);
    cudaGetSymbolAddress((void**)&p_sc,    g_scores);
    cudaGetSymbolAddress((void**)&p_probs, g_probs);
    cudaGetSymbolAddress((void**)&p_ctxh,  g_ctxh);
    cudaGetSymbolAddress((void**)&p_ffnh,  g_ffnh);
    cudaGetSymbolAddress((void**)&p_woth,  g_woth);
    cudaGetSymbolAddress((void**)&p_w1th,  g_w1th);
    cudaGetSymbolAddress((void**)&p_w2th,  g_w2th);

    cudaFuncSetAttribute(hgemm, cudaFuncAttributeMaxDynamicSharedMemorySize,
                         G_SMEM_BYTES);
    cudaFuncSetAttribute(scores_h, cudaFuncAttributeMaxDynamicSharedMemorySize,
                         S_SMEM_BYTES);
    cudaFuncSetAttribute(ctx_hgemm, cudaFuncAttributeMaxDynamicSharedMemorySize,
                         C_SMEM_BYTES);

    // 0) weight transposes -> fp16 K-major [N][K]
    transpose_h<<<dim3(Dd / 32, Dd / 64), dim3(32, 8)>>>(Wo, p_woth, Dd, Dd);
    transpose_h<<<dim3(DFF / 32, Dd / 64), dim3(32, 8)>>>(W1, p_w1th, Dd, DFF);
    transpose_h<<<dim3(Dd / 32, DFF / 64), dim3(32, 8)>>>(W2, p_w2th, DFF, Dd);
    repack_qkv_t_h<<<dim3(HDd / 32, Dd / 64, 12), dim3(32, 8)>>>(Wq, Wk, Wv, p_wqkvh);

    // 1) h = LN(x) -> fp16
    ln_kernel_h<<<BT, 256>>>(x, g1, be1, p_lnh);

    // 2) QKV = h @ Wqkv^T -> fp16
    hgemm<<<dim3(NQKV / 256, BT / 128), 512, G_SMEM_BYTES>>>(
        p_lnh, Dd, p_wqkvh, Dd,
        p_qkvh, NQKV, Dd, nullptr, nullptr, 0, 0, 1);

    // 3) scores = scale * q k^T, causal
    scores_h<<<dim3(Tt / 128, Tt / 128, Bb * Hh), 256, S_SMEM_BYTES>>>(
        p_qkvh, p_sc);

    // 4) softmax -> fp16 probs
    softmax_h<<<Bb * Hh * Tt, 128>>>(p_sc, p_probs);

    // 5) ctx = probs @ v
    ctx_hgemm<<<dim3(HDd / 128, Tt / 128, Bb * Hh), 256, C_SMEM_BYTES>>>(
        p_probs, p_qkvh, p_ctxh);

    // 6) x2 = x + ctx @ Wo^T + bo -> d_out (fp32)
    hgemm<<<dim3(Dd / 256, BT / 128), 512, G_SMEM_BYTES>>>(
        p_ctxh, Dd, p_woth, Dd,
        out, Dd, Dd, bo, x, Dd, 0, 0);

    // 7) h2 = LN(x2) -> fp16
    ln_kernel_h<<<BT, 256>>>(out, g2, be2, p_lnh);

    // 8) u = relu(h2 @ W1^T + b1) -> fp16
    hgemm<<<dim3(DFF / 256, BT / 128), 512, G_SMEM_BYTES>>>(
        p_lnh, Dd, p_w1th, Dd,
        p_ffnh, DFF, Dd, b1, nullptr, 0, 1, 1);

    // 9) out = x2 + u @ W2^T + b2 (fp32, resid in place)
    hgemm<<<dim3(Dd / 256, BT / 128), 512, G_SMEM_BYTES>>>(
        p_ffnh, DFF, p_w2th, DFF,
        out, Dd, DFF, b2, out, Dd, 0, 0);
}